// round 3
// baseline (speedup 1.0000x reference)
#include <cuda_runtime.h>
#include <math.h>

// Problem constants
#define NB 4
#define NS 1000
#define NF 256
#define UP 32
#define NT (NF * UP)   // 8192

// 2*pi as double (== 2.0*np.pi), and the fp32-quantized omega multiplier the
// reference effectively uses: fl32(2*pi/44100).
constexpr double kTwoPiD  = 6.283185307179586;
constexpr float  kOmC     = (float)(kTwoPiD / 44100.0);   // fl32(2pi/FS)
constexpr double kOmCD    = (double)kOmC;                 // exact double of that fp32
constexpr double kInv2PiD = 1.0 / kTwoPiD;
constexpr float  kInv2Pi  = (float)(1.0 / kTwoPiD);
constexpr float  kC1      = 6.28125f;                     // high part of 2pi (exact, 8 bits)
constexpr float  kC2      = (float)(kTwoPiD - (double)6.28125f);

// Static scratch
__device__ float g_freqT[NB][NF][NS];   // [b][f][s]
__device__ float g_ampT [NB][NF][NS];   // [b][f][s]
__device__ float g_P    [NB][NF][NS];   // wrapped phase at frame start, [-pi,pi]

// ---------------------------------------------------------------------------
// Transpose [B,S,F] -> [B,F,S]
// ---------------------------------------------------------------------------
__global__ void transpose_kernel(const float* __restrict__ freq,
                                 const float* __restrict__ amp) {
    __shared__ float tf[32][33];
    __shared__ float ta[32][33];
    int b  = blockIdx.z;
    int s0 = blockIdx.x * 32;
    int f0 = blockIdx.y * 32;
    int tx = threadIdx.x;   // 32
    int ty = threadIdx.y;   // 8

    #pragma unroll
    for (int r = ty; r < 32; r += 8) {
        int s = s0 + r;
        int f = f0 + tx;
        if (s < NS) {
            tf[r][tx] = freq[((long)b * NS + s) * NF + f];
            ta[r][tx] = amp [((long)b * NS + s) * NF + f];
        }
    }
    __syncthreads();
    #pragma unroll
    for (int r = ty; r < 32; r += 8) {
        int f = f0 + r;
        int s = s0 + tx;
        if (s < NS) {
            g_freqT[b][f][s] = tf[tx][r];
            g_ampT [b][f][s] = ta[tx][r];
        }
    }
}

// ---------------------------------------------------------------------------
// Frame-prefix kernel: exact (fp64) phase at each frame start, wrapped to
// [-pi,pi], stored as fp32.  One warp per (b,s) chain; lane l covers frames
// [8l, 8l+8).  Frame-f omega sum has the closed form
//   (4*x[f-1] + 24*x[f] + 4*x[f+1]) * omC      (boundaries via clamping)
// Warp-level fp64 inclusive scan gives the frame prefixes.
// Block = 8 warps = 8 consecutive s; smem staging for coalesced g_P stores.
// ---------------------------------------------------------------------------
__global__ void __launch_bounds__(256) frame_prefix_kernel(const float* __restrict__ freq) {
    __shared__ float smP[8][NF + 1];

    int tid  = threadIdx.x;
    int w    = tid >> 5;         // warp in block = chain index 0..7
    int lane = tid & 31;

    int chains_per_b = NS / 8;               // 125
    int b  = blockIdx.x / chains_per_b;
    int s0 = (blockIdx.x % chains_per_b) * 8;
    int s  = s0 + w;

    const float* row = freq + ((long)b * NS + s) * NF;

    int f0 = lane * 8;
    // Load x[f0-1 .. f0+8] with clamping (10 values)
    float xv[10];
    #pragma unroll
    for (int t = 0; t < 10; t++) {
        int f = f0 - 1 + t;
        f = f < 0 ? 0 : (f > NF - 1 ? NF - 1 : f);
        xv[t] = row[f];
    }

    // 8 frame sums in fp64 (clamped loads make boundary formulas automatic)
    double fs[8];
    double lane_sum = 0.0;
    #pragma unroll
    for (int k = 0; k < 8; k++) {
        double xm = (double)xv[k];
        double x0 = (double)xv[k + 1];
        double xp = (double)xv[k + 2];
        fs[k] = (4.0 * (xm + xp) + 24.0 * x0) * kOmCD;
        lane_sum += fs[k];
    }

    // Warp-inclusive scan of lane sums (fp64)
    double inc = lane_sum;
    #pragma unroll
    for (int d = 1; d < 32; d <<= 1) {
        double n = __shfl_up_sync(0xFFFFFFFFu, inc, d);
        if (lane >= d) inc += n;
    }
    double running = inc - lane_sum;   // exclusive prefix at frame f0

    // Emit wrapped fp32 frame-start phases
    #pragma unroll
    for (int k = 0; k < 8; k++) {
        double kk = rint(running * kInv2PiD);
        double wr = running - kk * kTwoPiD;
        smP[w][f0 + k] = (float)wr;
        running += fs[k];
    }
    __syncthreads();

    // Coalesced store: consecutive tid -> consecutive s (8 floats = 32B sector)
    int j = tid & 7;
    int fbase = tid >> 3;   // 0..31
    #pragma unroll
    for (int c = 0; c < 8; c++) {
        int f = c * 32 + fbase;
        g_P[b][f][s0 + j] = smP[j][f];
    }
}

// ---------------------------------------------------------------------------
// Synth kernel: block = (f, b); threads stride over s.  Per sample j the
// inclusive in-frame phase is P + omC*(A_j*xm + B_j*x0 + C_j*xp) with exact
// dyadic constants (no serial dependency).  Wrap (k<=5) + __sinf, 32 register
// accumulators, deterministic reduction.
// ---------------------------------------------------------------------------
__global__ void __launch_bounds__(256) synth_kernel(float* __restrict__ out,
                                                    const float* __restrict__ initp) {
    int f = blockIdx.x;   // 0..255
    int b = blockIdx.y;   // 0..3
    int tid  = threadIdx.x;
    int lane = tid & 31;
    int warp = tid >> 5;

    __shared__ float wsum[8][32];

    float acc[32];
    #pragma unroll
    for (int j = 0; j < 32; j++) acc[j] = 0.0f;

    int fm  = (f > 0) ? f - 1 : 0;
    int fp_ = (f < NF - 1) ? f + 1 : NF - 1;

    for (int s = tid; s < NS; s += 256) {
        float P   = g_P[b][f][s];
        float pi0 = initp[b * NS + s];
        P += pi0;   // init phase (zeros in practice; harmless, accurate)
        float xm = g_freqT[b][fm ][s];
        float x0 = g_freqT[b][f  ][s];
        float xp = g_freqT[b][fp_][s];
        float am = g_ampT[b][fm ][s];
        float a0 = g_ampT[b][f  ][s];
        float ap = g_ampT[b][fp_][s];

        float dA0 = a0 - am;   // amp interp slopes
        float dA1 = ap - a0;

        #pragma unroll
        for (int j = 0; j < 32; j++) {
            // Exact dyadic cumulative-weight constants
            float A, B, C, wa;
            if (j < 16) {
                A  = (float)((j + 1) * (31 - j)) * 0.015625f;
                B  = (float)((j + 1) * (j + 33)) * 0.015625f;
                C  = 0.0f;
                wa = ((float)j + 16.5f) * 0.03125f;
            } else {
                A  = 4.0f;
                B  = 12.0f + (float)((j - 15) * (79 - j)) * 0.015625f;
                C  = (float)((j - 15) * (j - 15)) * 0.015625f;
                wa = ((float)j - 15.5f) * 0.03125f;
            }

            float t = A * xm;
            t = fmaf(B, x0, t);
            t = fmaf(C, xp, t);
            float ph = fmaf(kOmC, t, P);

            // wrap to [-pi,pi]: k in [0..5]
            float k = rintf(ph * kInv2Pi);
            ph = fmaf(k, -kC1, ph);
            ph = fmaf(k, -kC2, ph);

            float sv = __sinf(ph);
            float av = (j < 16) ? fmaf(wa, dA0, am) : fmaf(wa, dA1, a0);
            acc[j] = fmaf(av, sv, acc[j]);
        }
    }

    // Deterministic reduction: butterfly per j; lane j keeps warp total for j.
    float mine = 0.0f;
    #pragma unroll
    for (int j = 0; j < 32; j++) {
        float v = acc[j];
        v += __shfl_xor_sync(0xFFFFFFFFu, v, 16);
        v += __shfl_xor_sync(0xFFFFFFFFu, v, 8);
        v += __shfl_xor_sync(0xFFFFFFFFu, v, 4);
        v += __shfl_xor_sync(0xFFFFFFFFu, v, 2);
        v += __shfl_xor_sync(0xFFFFFFFFu, v, 1);
        if (lane == j) mine = v;
    }
    wsum[warp][lane] = mine;
    __syncthreads();

    if (tid < 32) {
        float t = 0.0f;
        #pragma unroll
        for (int w = 0; w < 8; w++) t += wsum[w][tid];
        out[(long)b * NT + f * 32 + tid] = t;
    }
}

// ---------------------------------------------------------------------------
extern "C" void kernel_launch(void* const* d_in, const int* in_sizes, int n_in,
                              void* d_out, int out_size) {
    const float* freq  = (const float*)d_in[0];   // [4,1000,256]
    const float* amp   = (const float*)d_in[1];   // [4,1000,256]
    const float* initp = (const float*)d_in[2];   // [4,1000]
    float* out = (float*)d_out;                   // [4,1,8192]
    (void)in_sizes; (void)n_in; (void)out_size;

    transpose_kernel<<<dim3((NS + 31) / 32, NF / 32, NB), dim3(32, 8)>>>(freq, amp);
    frame_prefix_kernel<<<(NB * NS) / 8, 256>>>(freq);
    synth_kernel<<<dim3(NF, NB), 256>>>(out, initp);
}

// round 6
// speedup vs baseline: 1.3089x; 1.3089x over previous
#include <cuda_runtime.h>
#include <math.h>

#define NB 4
#define NS 1000
#define NF 256
#define NT 8192

// --- constants ---
constexpr double kTwoPiD  = 6.283185307179586;
constexpr float  kOmC     = (float)(kTwoPiD / 44100.0);       // fl32(2pi/FS), reference's omega quantum
constexpr double kTCd     = (double)kOmC / kTwoPiD;           // turns per Hz per sample (exact intent)
constexpr float  kTCh     = (float)kTCd;                      // hi part
constexpr float  kTCl     = (float)(kTCd - (double)kTCh);     // lo part (kills systematic drift)
constexpr float  kTwoPiF  = (float)kTwoPiD;
constexpr float  kInv2PiF = (float)(1.0 / kTwoPiD);
constexpr float  kMagic   = 12582912.0f;                      // 2^23 + 2^22: RN-to-integer trick

// --- static scratch (12.3 MB) ---
__device__ float g_freqT[NB][NF][NS];   // freq * kTC (turn increment per sample), [b][f][s]
__device__ float g_ampT [NB][NF][NS];   // amplitude, [b][f][s]
__device__ float g_P    [NB][NF][NS];   // wrapped frame-start phase in TURNS, [-0.5, 0.5]

// round-to-nearest-integer via magic add (valid |x| < 2^21), full-rate FADDs
__device__ __forceinline__ float rni_magic(float x) {
    float r = __fadd_rn(x, kMagic);
    return __fadd_rn(r, -kMagic);
}
__device__ __forceinline__ float wrap_turns(float x) {
    return __fadd_rn(x, -rni_magic(x));
}

// ---------------------------------------------------------------------------
// Fused kernel: per-(b,s) frame-start phase prefixes (wrapped, turns) AND
// transposed (scaled) freq / amp.  Block = 8 warps = 8 sines.  Warp w owns
// sine s0+w; lane l owns frames {c*32+l : c=0..7} (chunk-major -> coalesced
// row loads).  Frame-f omega sum closed form: (4(x[f-1]+x[f+1]) + 24 x[f]).
// Warp-wide wrapped scan per chunk, chunks chained via broadcast total.
// ALL warp collectives are in uniform control flow (divergent shfl traps).
// smem staged with XOR swizzle (f ^ (w<<2)) -> conflict-free both sides.
// ---------------------------------------------------------------------------
__global__ void __launch_bounds__(256) prep_kernel(const float* __restrict__ freq,
                                                   const float* __restrict__ amp) {
    __shared__ float smP[8][256];
    __shared__ float smF[8][256];
    __shared__ float smA[8][256];

    int tid  = threadIdx.x;
    int w    = tid >> 5;
    int lane = tid & 31;

    int b  = blockIdx.x / (NS / 8);
    int s0 = (blockIdx.x % (NS / 8)) * 8;
    int s  = s0 + w;

    const float* frow = freq + ((long)b * NS + s) * NF;
    const float* arow = amp  + ((long)b * NS + s) * NF;

    float x[8], a[8];
    #pragma unroll
    for (int c = 0; c < 8; c++) {
        x[c] = frow[c * 32 + lane];   // coalesced 128B
        a[c] = arow[c * 32 + lane];
    }

    float run = 0.0f;   // wrapped running phase at chunk start (warp-uniform)
    #pragma unroll
    for (int c = 0; c < 8; c++) {
        float xc = x[c];

        // Uniform warp collectives first (c is compile-time -> static indexing)
        float prev_last  = __shfl_sync(0xFFFFFFFFu, x[c > 0 ? c - 1 : 0], 31);
        float next_first = __shfl_sync(0xFFFFFFFFu, x[c < 7 ? c + 1 : 7], 0);
        float xmv = __shfl_up_sync  (0xFFFFFFFFu, xc, 1);
        float xpv = __shfl_down_sync(0xFFFFFFFFu, xc, 1);

        // Edge-lane patch with plain selects (no collectives under divergence)
        if (lane == 0)  xmv = (c == 0) ? xc : prev_last;
        if (lane == 31) xpv = (c == 7) ? xc : next_first;

        // frame sum in turns, two-float constant, wrapped to [-0.5, 0.5]
        float t  = fmaf(24.0f, xc, 4.0f * (xmv + xpv));
        float fs = fmaf(t, kTCh, t * kTCl);
        float fsw = wrap_turns(fs);

        // warp inclusive scan (plain adds; |sum| <= 16 turns)
        float inc = fsw;
        #pragma unroll
        for (int d = 1; d < 32; d <<= 1) {
            float n = __shfl_up_sync(0xFFFFFFFFu, inc, d);
            if (lane >= d) inc += n;
        }
        float excl = inc - fsw;
        float Pf = wrap_turns(run + excl);

        int idx = (c * 32 + lane) ^ (w << 2);   // swizzle: conflict-free
        smP[w][idx] = Pf;
        smF[w][idx] = fmaf(xc, kTCl, xc * kTCh);   // scaled: turn increment / sample
        smA[w][idx] = a[c];

        float tot = __shfl_sync(0xFFFFFFFFu, inc, 31);
        run = wrap_turns(run + tot);
    }
    __syncthreads();

    // coalesced transposed stores: consecutive tid -> consecutive s
    int j  = tid & 7;        // s offset
    int fi = tid >> 3;       // 0..31
    #pragma unroll
    for (int c2 = 0; c2 < 8; c2++) {
        int f  = c2 * 32 + fi;
        int ix = f ^ (j << 2);
        g_P    [b][f][s0 + j] = smP[j][ix];
        g_freqT[b][f][s0 + j] = smF[j][ix];
        g_ampT [b][f][s0 + j] = smA[j][ix];
    }
}

// ---------------------------------------------------------------------------
// Synth kernel: block = (f, b); threads stride over s.  Incremental phase in
// turns: ph += inc; inc += dinc (slope switch at j=16).  Wrap via magic round,
// scale by 2*pi, __sinf.  32 register accumulators, smem transpose reduction.
// ---------------------------------------------------------------------------
__global__ void __launch_bounds__(256) synth_kernel(float* __restrict__ out,
                                                    const float* __restrict__ initp) {
    __shared__ float red[256][33];

    int f = blockIdx.x;
    int b = blockIdx.y;
    int tid = threadIdx.x;

    float acc[32];
    #pragma unroll
    for (int j = 0; j < 32; j++) acc[j] = 0.0f;

    int fm  = (f > 0) ? f - 1 : 0;
    int fp_ = (f < NF - 1) ? f + 1 : NF - 1;

    for (int s = tid; s < NS; s += 256) {
        float P   = g_P[b][f][s];
        float pi0 = initp[b * NS + s];
        P = fmaf(pi0, kInv2PiF, P);     // init phase (rad) -> turns
        P = wrap_turns(P);

        float xm = g_freqT[b][fm ][s];
        float x0 = g_freqT[b][f  ][s];
        float xp = g_freqT[b][fp_][s];
        float am = g_ampT[b][fm ][s];
        float a0 = g_ampT[b][f  ][s];
        float ap = g_ampT[b][fp_][s];

        float d0 = x0 - xm, d1 = xp - x0;
        float inc = fmaf(0.515625f, d0, xm);     // v at j=0 (w0 = 0.5 + 0.5/32)
        float dnc = d0 * 0.03125f;
        float da  = a0 - am;
        float av  = fmaf(0.515625f, da, am);
        float dav = da * 0.03125f;

        float ph = P;
        #pragma unroll
        for (int j = 0; j < 32; j++) {
            if (j == 16) {                       // compile-time branch (unrolled)
                inc = fmaf(0.015625f, d1, x0);   // v at j=16 (w16 = 0.5/32)
                dnc = d1 * 0.03125f;
                da  = ap - a0;
                av  = fmaf(0.015625f, da, a0);
                dav = da * 0.03125f;
            }
            ph = __fadd_rn(ph, inc);             // inclusive phase (turns)
            float tw = wrap_turns(ph);           // [-0.5, 0.5]
            acc[j] = fmaf(av, __sinf(tw * kTwoPiF), acc[j]);
            inc = __fadd_rn(inc, dnc);
            av  = __fadd_rn(av, dav);
        }
    }

    // --- reduction: smem transpose (conflict-free via +1 padding) ---
    #pragma unroll
    for (int j = 0; j < 32; j++) red[tid][j] = acc[j];
    __syncthreads();

    int j = tid & 31, g = tid >> 5;
    float p = 0.0f;
    #pragma unroll
    for (int i = 0; i < 32; i++) p += red[g * 32 + i][j];
    __syncthreads();

    ((float*)red)[g * 32 + j] = p;
    __syncthreads();

    if (tid < 32) {
        float t = 0.0f;
        #pragma unroll
        for (int g2 = 0; g2 < 8; g2++) t += ((float*)red)[g2 * 32 + tid];
        out[((long)b << 13) + (f << 5) + tid] = t;
    }
}

// ---------------------------------------------------------------------------
extern "C" void kernel_launch(void* const* d_in, const int* in_sizes, int n_in,
                              void* d_out, int out_size) {
    const float* freq  = (const float*)d_in[0];   // [4,1000,256]
    const float* amp   = (const float*)d_in[1];   // [4,1000,256]
    const float* initp = (const float*)d_in[2];   // [4,1000]
    float* out = (float*)d_out;                   // [4,1,8192]
    (void)in_sizes; (void)n_in; (void)out_size;

    prep_kernel<<<NB * (NS / 8), 256>>>(freq, amp);
    synth_kernel<<<dim3(NF, NB), 256>>>(out, initp);
}

// round 8
// speedup vs baseline: 1.4161x; 1.0819x over previous
#include <cuda_runtime.h>
#include <math.h>

#define NB 4
#define NS 1000
#define NF 256
#define NT 8192

// --- constants ---
constexpr double kTwoPiD  = 6.283185307179586;
constexpr float  kOmC     = (float)(kTwoPiD / 44100.0);       // fl32(2pi/FS): reference's omega quantum
constexpr double kTCd     = (double)kOmC / kTwoPiD;           // turns per Hz per sample
constexpr float  kTCh     = (float)kTCd;
constexpr float  kTCl     = (float)(kTCd - (double)kTCh);
constexpr float  kTwoPiF  = (float)kTwoPiD;
constexpr float  kMagic   = 12582912.0f;                      // 2^23 + 2^22

// --- static scratch (16.4 MB) ---
__device__ float g_freqR[NB][NF][NS];   // omega (radians/sample), [b][f][s]
__device__ float g_ampT [NB][NF][NS];   // amplitude, [b][f][s]
__device__ float g_P    [NB][NF][NS];   // wrapped frame-START phase, turns [-0.5,0.5]
__device__ float g_Pm   [NB][NF][NS];   // wrapped MID-frame phase (after sample 15), turns

__device__ __forceinline__ float rni_magic(float x) {
    float r = __fadd_rn(x, kMagic);
    return __fadd_rn(r, -kMagic);
}
__device__ __forceinline__ float wrap_turns(float x) {
    return __fadd_rn(x, -rni_magic(x));
}

// ---------------------------------------------------------------------------
// Prep: frame-start + mid-frame phase prefixes (wrapped, turns) AND transposed
// omega / amp.  Warp w owns sine s0+w; lane l owns frames {c*32+l}.
// Frame sum closed form: (4(x[f-1]+x[f+1]) + 24 x[f]); first half: 4x[f-1]+12x[f].
// All warp collectives in uniform control flow.  XOR-swizzled smem staging.
// ---------------------------------------------------------------------------
__global__ void __launch_bounds__(256) prep_kernel(const float* __restrict__ freq,
                                                   const float* __restrict__ amp) {
    __shared__ float smP [8][256];
    __shared__ float smPm[8][256];
    __shared__ float smF [8][256];
    __shared__ float smA [8][256];

    int tid  = threadIdx.x;
    int w    = tid >> 5;
    int lane = tid & 31;

    int b  = blockIdx.x / (NS / 8);
    int s0 = (blockIdx.x % (NS / 8)) * 8;
    int s  = s0 + w;

    const float* frow = freq + ((long)b * NS + s) * NF;
    const float* arow = amp  + ((long)b * NS + s) * NF;

    float x[8], a[8];
    #pragma unroll
    for (int c = 0; c < 8; c++) {
        x[c] = frow[c * 32 + lane];
        a[c] = arow[c * 32 + lane];
    }

    float run = 0.0f;
    #pragma unroll
    for (int c = 0; c < 8; c++) {
        float xc = x[c];

        float prev_last  = __shfl_sync(0xFFFFFFFFu, x[c > 0 ? c - 1 : 0], 31);
        float next_first = __shfl_sync(0xFFFFFFFFu, x[c < 7 ? c + 1 : 7], 0);
        float xmv = __shfl_up_sync  (0xFFFFFFFFu, xc, 1);
        float xpv = __shfl_down_sync(0xFFFFFFFFu, xc, 1);
        if (lane == 0)  xmv = (c == 0) ? xc : prev_last;
        if (lane == 31) xpv = (c == 7) ? xc : next_first;

        // full-frame sum (turns, wrapped) and first-half sum
        float t  = fmaf(24.0f, xc, 4.0f * (xmv + xpv));
        float fs = fmaf(t, kTCh, t * kTCl);
        float fsw = wrap_turns(fs);

        float th = fmaf(12.0f, xc, 4.0f * xmv);
        float hs = fmaf(th, kTCh, th * kTCl);
        float hsw = wrap_turns(hs);

        // warp inclusive scan
        float inc = fsw;
        #pragma unroll
        for (int d = 1; d < 32; d <<= 1) {
            float n = __shfl_up_sync(0xFFFFFFFFu, inc, d);
            if (lane >= d) inc += n;
        }
        float excl = inc - fsw;
        float Pf = wrap_turns(run + excl);
        float Pm = wrap_turns(Pf + hsw);

        int idx = (c * 32 + lane) ^ (w << 2);
        smP [w][idx] = Pf;
        smPm[w][idx] = Pm;
        smF [w][idx] = xc * kOmC;    // radians/sample, exact reference omega
        smA [w][idx] = a[c];

        float tot = __shfl_sync(0xFFFFFFFFu, inc, 31);
        run = wrap_turns(run + tot);
    }
    __syncthreads();

    int j  = tid & 7;
    int fi = tid >> 3;
    #pragma unroll
    for (int c2 = 0; c2 < 8; c2++) {
        int f  = c2 * 32 + fi;
        int ix = f ^ (j << 2);
        g_P    [b][f][s0 + j] = smP [j][ix];
        g_Pm   [b][f][s0 + j] = smPm[j][ix];
        g_freqR[b][f][s0 + j] = smF [j][ix];
        g_ampT [b][f][s0 + j] = smA [j][ix];
    }
}

// ---------------------------------------------------------------------------
// Synth: block = (half-frame, b).  16 accumulators/thread, radians domain,
// NO per-sample wrap (|arg| <= ~15 rad, MUFU.SIN handles it).  Inner loop:
// ph+=inc; sin; fmaf; inc+=dnc; av+=dav  (5 issue slots + MUFU).
// ---------------------------------------------------------------------------
__global__ void __launch_bounds__(256) synth_kernel(float* __restrict__ out,
                                                    const float* __restrict__ initp) {
    __shared__ float red[256][17];

    int fh   = blockIdx.x;           // 0..511
    int b    = blockIdx.y;
    int f    = fh >> 1;
    int half = fh & 1;
    int tid  = threadIdx.x;

    // interp endpoints for this half
    int ia = half ? f : (f > 0 ? f - 1 : 0);
    int ib = half ? (f < NF - 1 ? f + 1 : NF - 1) : f;
    const float w0 = half ? 0.015625f : 0.515625f;   // first-sample weight

    const float* Pbase = half ? &g_Pm[b][f][0] : &g_P[b][f][0];
    const float* Xa = &g_freqR[b][ia][0];
    const float* Xb = &g_freqR[b][ib][0];
    const float* Aa = &g_ampT [b][ia][0];
    const float* Ab = &g_ampT [b][ib][0];
    const float* I0 = initp + b * NS;

    float acc[16];
    #pragma unroll
    for (int j = 0; j < 16; j++) acc[j] = 0.0f;

    for (int s = tid; s < NS; s += 256) {
        float Pt  = Pbase[s];
        float pi0 = I0[s];
        float ph  = fmaf(Pt, kTwoPiF, pi0);      // radians, |ph| ~<= pi (+init)

        float xa = Xa[s], xb = Xb[s];
        float aa = Aa[s], ab = Ab[s];

        float d   = xb - xa;
        float inc = fmaf(w0, d, xa);             // omega at first sample of half
        float dnc = d * 0.03125f;
        float da  = ab - aa;
        float av  = fmaf(w0, da, aa);
        float dav = da * 0.03125f;

        #pragma unroll
        for (int j = 0; j < 16; j++) {
            ph = __fadd_rn(ph, inc);
            acc[j] = fmaf(av, __sinf(ph), acc[j]);
            inc = __fadd_rn(inc, dnc);
            av  = __fadd_rn(av, dav);
        }
    }

    // --- reduction over 256 threads for 16 sample slots ---
    #pragma unroll
    for (int j = 0; j < 16; j++) red[tid][j] = acc[j];
    __syncthreads();

    int j = tid & 15, r = tid >> 4;              // 16 groups of 16 rows
    float p = 0.0f;
    #pragma unroll
    for (int i = 0; i < 16; i++) p += red[r * 16 + i][j];
    __syncthreads();

    ((float*)red)[r * 16 + j] = p;
    __syncthreads();

    if (tid < 16) {
        float t = 0.0f;
        #pragma unroll
        for (int g2 = 0; g2 < 16; g2++) t += ((float*)red)[g2 * 16 + tid];
        out[((long)b << 13) + (f << 5) + (half << 4) + tid] = t;
    }
}

// ---------------------------------------------------------------------------
extern "C" void kernel_launch(void* const* d_in, const int* in_sizes, int n_in,
                              void* d_out, int out_size) {
    const float* freq  = (const float*)d_in[0];   // [4,1000,256]
    const float* amp   = (const float*)d_in[1];   // [4,1000,256]
    const float* initp = (const float*)d_in[2];   // [4,1000]
    float* out = (float*)d_out;                   // [4,1,8192]
    (void)in_sizes; (void)n_in; (void)out_size;

    prep_kernel<<<NB * (NS / 8), 256>>>(freq, amp);
    synth_kernel<<<dim3(NF * 2, NB), 256>>>(out, initp);
}